// round 1
// baseline (speedup 1.0000x reference)
#include <cuda_runtime.h>

// Problem constants
#define B_ 4
#define N_ 1024
#define H_ 64
#define D_ 64
#define FE_ 16

// Scratch (allocation-free: __device__ globals)
__device__ float g_z[B_ * N_ * D_];       // 1 MB
__device__ float g_si[B_ * N_];
__device__ float g_sj[B_ * N_];
__device__ float g_rowsum[B_ * N_];
__device__ float g_total[B_];

// ---------------------------------------------------------------------------
// k_z: z[b,n,d] = sum_h h0[b,n,h] * w_fc[d,h];  sj = z.a1, si = z.a2
// grid = B*N blocks, 64 threads (thread = d)
// ---------------------------------------------------------------------------
__global__ void k_z(const float* __restrict__ h0,
                    const float* __restrict__ w_fc,
                    const float* __restrict__ w_attn) {
    __shared__ float h0s[H_];
    __shared__ float red1[2], red2[2];
    const int row = blockIdx.x;      // b*N + n
    const int d = threadIdx.x;       // 0..63

    h0s[d] = h0[row * H_ + d];
    __syncthreads();

    const float* w = w_fc + d * H_;
    float acc = 0.f;
#pragma unroll
    for (int h = 0; h < H_; ++h) acc = fmaf(h0s[h], w[h], acc);

    g_z[row * D_ + d] = acc;

    float c1 = acc * __ldg(&w_attn[d]);        // a1[d] -> sj
    float c2 = acc * __ldg(&w_attn[D_ + d]);   // a2[d] -> si
#pragma unroll
    for (int o = 16; o; o >>= 1) {
        c1 += __shfl_down_sync(0xffffffffu, c1, o);
        c2 += __shfl_down_sync(0xffffffffu, c2, o);
    }
    if ((d & 31) == 0) { red1[d >> 5] = c1; red2[d >> 5] = c2; }
    __syncthreads();
    if (d == 0) {
        g_sj[row] = red1[0] + red1[1];
        g_si[row] = red2[0] + red2[1];
    }
}

// ---------------------------------------------------------------------------
// k_row: the big pass. One block per (b,i) row; streams 64KB of e.
// rowsum[b,i] = sum_j exp(leaky_relu(si[b,i] + sj[b,j] + <e[b,i,j,:], a3>))
// (no max subtraction: softmax ratio is invariant; values are far below
//  fp32 exp overflow for this input distribution)
// grid = B*N blocks, 256 threads
// ---------------------------------------------------------------------------
__global__ void k_row(const float* __restrict__ e,
                      const float* __restrict__ w_attn) {
    __shared__ float a3[FE_];
    __shared__ float sjs[N_];
    __shared__ float red[256];

    const int row = blockIdx.x;      // b*N + i
    const int b = row >> 10;
    const int t = threadIdx.x;

    if (t < FE_) a3[t] = w_attn[2 * D_ + t];
#pragma unroll
    for (int j = t; j < N_; j += 256) sjs[j] = g_sj[b * N_ + j];
    __syncthreads();

    const float si = g_si[row];
    // e row: N_ * FE_ floats = N_ * 4 float4
    const float4* e4 = reinterpret_cast<const float4*>(e) + (size_t)row * N_ * 4;

    float acc = 0.f;
#pragma unroll
    for (int j = t; j < N_; j += 256) {
        const float4 v0 = e4[j * 4 + 0];
        const float4 v1 = e4[j * 4 + 1];
        const float4 v2 = e4[j * 4 + 2];
        const float4 v3 = e4[j * 4 + 3];
        float se = v0.x * a3[0] + v0.y * a3[1] + v0.z * a3[2] + v0.w * a3[3];
        se = fmaf(v1.x, a3[4], se); se = fmaf(v1.y, a3[5], se);
        se = fmaf(v1.z, a3[6], se); se = fmaf(v1.w, a3[7], se);
        se = fmaf(v2.x, a3[8], se); se = fmaf(v2.y, a3[9], se);
        se = fmaf(v2.z, a3[10], se); se = fmaf(v2.w, a3[11], se);
        se = fmaf(v3.x, a3[12], se); se = fmaf(v3.y, a3[13], se);
        se = fmaf(v3.z, a3[14], se); se = fmaf(v3.w, a3[15], se);
        float s = si + sjs[j] + se;
        s = (s >= 0.f) ? s : 0.01f * s;   // leaky_relu, slope 0.01
        acc += __expf(s);
    }

    // deterministic block tree reduction
    red[t] = acc;
    __syncthreads();
#pragma unroll
    for (int o = 128; o >= 1; o >>= 1) {
        if (t < o) red[t] += red[t + o];
        __syncthreads();
    }
    if (t == 0) g_rowsum[row] = red[0];
}

// ---------------------------------------------------------------------------
// k_total: total[b] = sum_i rowsum[b,i]  (deterministic, no atomics)
// grid = B blocks, 256 threads
// ---------------------------------------------------------------------------
__global__ void k_total() {
    __shared__ float red[256];
    const int b = blockIdx.x;
    const int t = threadIdx.x;
    float acc = 0.f;
#pragma unroll
    for (int i = t; i < N_; i += 256) acc += g_rowsum[b * N_ + i];
    red[t] = acc;
    __syncthreads();
#pragma unroll
    for (int o = 128; o >= 1; o >>= 1) {
        if (t < o) red[t] += red[t + o];
        __syncthreads();
    }
    if (t == 0) g_total[b] = red[0];
}

// ---------------------------------------------------------------------------
// k_out: out[b,i,d] = (rowsum[b,i] / total[b]) * z[b,i,d]
// ---------------------------------------------------------------------------
__global__ void k_out(float* __restrict__ out) {
    const int idx = blockIdx.x * 256 + threadIdx.x;   // < B*N*D
    const int row = idx >> 6;     // b*N + i
    const int b = row >> 10;
    out[idx] = g_rowsum[row] * (1.0f / g_total[b]) * g_z[idx];
}

// ---------------------------------------------------------------------------
extern "C" void kernel_launch(void* const* d_in, const int* in_sizes, int n_in,
                              void* d_out, int out_size) {
    const float* h0     = (const float*)d_in[0];   // (B,N,H)
    const float* e      = (const float*)d_in[1];   // (B,N,N,FE)
    const float* w_fc   = (const float*)d_in[2];   // (D,H)
    const float* w_attn = (const float*)d_in[3];   // (2D+FE,)
    float* out = (float*)d_out;                    // (B,N,D)

    k_z<<<B_ * N_, 64>>>(h0, w_fc, w_attn);
    k_row<<<B_ * N_, 256>>>(e, w_attn);
    k_total<<<B_, 256>>>();
    k_out<<<(B_ * N_ * D_) / 256, 256>>>(out);
}

// round 2
// speedup vs baseline: 1.0525x; 1.0525x over previous
#include <cuda_runtime.h>

// Problem constants
#define B_ 4
#define N_ 1024
#define H_ 64
#define D_ 64
#define FE_ 16

// Scratch (allocation-free: __device__ globals)
__device__ float g_z[B_ * N_ * D_];       // 1 MB
__device__ float g_si[B_ * N_];
__device__ float g_sj[B_ * N_];
__device__ float g_rowsum[B_ * N_];
__device__ float g_total[B_];

// ---------------------------------------------------------------------------
// k_z: z[b,n,d] = sum_h h0[b,n,h] * w_fc[d,h];  sj = z.a1, si = z.a2
// grid = B*N blocks, 64 threads (thread = d)
// ---------------------------------------------------------------------------
__global__ void k_z(const float* __restrict__ h0,
                    const float* __restrict__ w_fc,
                    const float* __restrict__ w_attn) {
    __shared__ float h0s[H_];
    __shared__ float red1[2], red2[2];
    const int row = blockIdx.x;      // b*N + n
    const int d = threadIdx.x;       // 0..63

    h0s[d] = h0[row * H_ + d];
    __syncthreads();

    const float* w = w_fc + d * H_;
    float acc = 0.f;
#pragma unroll
    for (int h = 0; h < H_; ++h) acc = fmaf(h0s[h], w[h], acc);

    g_z[row * D_ + d] = acc;

    float c1 = acc * __ldg(&w_attn[d]);        // a1[d] -> sj
    float c2 = acc * __ldg(&w_attn[D_ + d]);   // a2[d] -> si
#pragma unroll
    for (int o = 16; o; o >>= 1) {
        c1 += __shfl_down_sync(0xffffffffu, c1, o);
        c2 += __shfl_down_sync(0xffffffffu, c2, o);
    }
    if ((d & 31) == 0) { red1[d >> 5] = c1; red2[d >> 5] = c2; }
    __syncthreads();
    if (d == 0) {
        g_sj[row] = red1[0] + red1[1];
        g_si[row] = red2[0] + red2[1];
    }
}

// ---------------------------------------------------------------------------
// k_row v2: one block per (b,i) row, 256 threads, streams 64KB of e with
// FULLY COALESCED lane-contiguous float4 loads (4 wavefronts/LDG, not 16).
// Each float4 covers features 4*(lane&3)..+3 of j = idx4>>2; the dot product
// is completed across the 4-lane group with two shfl_xor. All 4 lanes then
// hold the same se, compute exp redundantly; final rowsum scaled by 0.25.
// rowsum[b,i] = sum_j exp(leaky_relu(si[b,i] + sj[b,j] + <e[b,i,j,:], a3>))
// (no max subtraction: softmax ratio invariant; fp32 exp can't overflow here)
// ---------------------------------------------------------------------------
__global__ void __launch_bounds__(256) k_row(const float* __restrict__ e,
                                             const float* __restrict__ w_attn) {
    __shared__ float sjs[N_];
    __shared__ float red[8];

    const int row = blockIdx.x;      // b*N + i
    const int b = row >> 10;
    const int t = threadIdx.x;
    const int lane = t & 31;
    const int w = t >> 5;

#pragma unroll
    for (int j = t; j < N_; j += 256) sjs[j] = g_sj[b * N_ + j];
    __syncthreads();

    // per-lane slice of a3 (fixed across iterations since 256 % 4 == 0)
    const int fg = (lane & 3) * 4;
    const float af0 = __ldg(&w_attn[2 * D_ + fg + 0]);
    const float af1 = __ldg(&w_attn[2 * D_ + fg + 1]);
    const float af2 = __ldg(&w_attn[2 * D_ + fg + 2]);
    const float af3 = __ldg(&w_attn[2 * D_ + fg + 3]);

    const float si = g_si[row];
    // e row: N_*FE_ floats = 4096 float4
    const float4* e4 = reinterpret_cast<const float4*>(e) + (size_t)row * (N_ * 4);

    float acc = 0.f;
#pragma unroll 8
    for (int idx4 = t; idx4 < N_ * 4; idx4 += 256) {
        const float4 v = __ldcs(&e4[idx4]);          // streaming: no L2 reuse
        float p = v.x * af0;
        p = fmaf(v.y, af1, p);
        p = fmaf(v.z, af2, p);
        p = fmaf(v.w, af3, p);
        // complete the 16-feature dot across the 4-lane group
        p += __shfl_xor_sync(0xffffffffu, p, 1);
        p += __shfl_xor_sync(0xffffffffu, p, 2);
        const int j = idx4 >> 2;
        float s = si + sjs[j] + p;
        s = (s >= 0.f) ? s : 0.01f * s;              // leaky_relu
        acc += __expf(s);                            // 4x redundant; /4 at end
    }

    // block reduction (deterministic)
#pragma unroll
    for (int o = 16; o; o >>= 1) acc += __shfl_down_sync(0xffffffffu, acc, o);
    if (lane == 0) red[w] = acc;
    __syncthreads();
    if (t == 0) {
        float s = 0.f;
#pragma unroll
        for (int k = 0; k < 8; ++k) s += red[k];
        g_rowsum[row] = 0.25f * s;
    }
}

// ---------------------------------------------------------------------------
// k_total: total[b] = sum_i rowsum[b,i]  (deterministic, no atomics)
// grid = B blocks, 256 threads
// ---------------------------------------------------------------------------
__global__ void k_total() {
    __shared__ float red[256];
    const int b = blockIdx.x;
    const int t = threadIdx.x;
    float acc = 0.f;
#pragma unroll
    for (int i = t; i < N_; i += 256) acc += g_rowsum[b * N_ + i];
    red[t] = acc;
    __syncthreads();
#pragma unroll
    for (int o = 128; o >= 1; o >>= 1) {
        if (t < o) red[t] += red[t + o];
        __syncthreads();
    }
    if (t == 0) g_total[b] = red[0];
}

// ---------------------------------------------------------------------------
// k_out: out[b,i,d] = (rowsum[b,i] / total[b]) * z[b,i,d]   (float4)
// grid = B*N*D/4/256 = 256 blocks
// ---------------------------------------------------------------------------
__global__ void k_out(float* __restrict__ out) {
    const int idx = blockIdx.x * 256 + threadIdx.x;   // float4 index < 65536
    const int row = idx >> 4;     // b*N + i   (16 float4 per row)
    const int b = row >> 10;
    const float scale = g_rowsum[row] * (1.0f / g_total[b]);
    const float4 z = reinterpret_cast<const float4*>(g_z)[idx];
    float4 o;
    o.x = scale * z.x; o.y = scale * z.y; o.z = scale * z.z; o.w = scale * z.w;
    reinterpret_cast<float4*>(out)[idx] = o;
}

// ---------------------------------------------------------------------------
extern "C" void kernel_launch(void* const* d_in, const int* in_sizes, int n_in,
                              void* d_out, int out_size) {
    const float* h0     = (const float*)d_in[0];   // (B,N,H)
    const float* e      = (const float*)d_in[1];   // (B,N,N,FE)
    const float* w_fc   = (const float*)d_in[2];   // (D,H)
    const float* w_attn = (const float*)d_in[3];   // (2D+FE,)
    float* out = (float*)d_out;                    // (B,N,D)

    k_z<<<B_ * N_, 64>>>(h0, w_fc, w_attn);
    k_row<<<B_ * N_, 256>>>(e, w_attn);
    k_total<<<B_, 256>>>();
    k_out<<<(B_ * N_ * D_) / 1024, 256>>>(out);
}

// round 3
// speedup vs baseline: 2.0226x; 1.9218x over previous
#include <cuda_runtime.h>

// Problem constants
#define B_ 4
#define N_ 1024
#define H_ 64
#define D_ 64
#define FE_ 16

// Scratch (allocation-free: __device__ globals)
__device__ float g_z[B_ * N_ * D_];       // 1 MB
__device__ float g_si[B_ * N_];
__device__ float g_sj[B_ * N_];
__device__ float g_rowsum[B_ * N_];

// ---------------------------------------------------------------------------
// k_z v2: tiled GEMM. 256 blocks x 256 threads, 16 rows per block.
// z[r,d] = sum_h h0[r,h] * w_fc[d,h];  sj[r] = z[r,:].a1, si[r] = z[r,:].a2
// w_fc staged TRANSPOSED in smem (wT[h][d]) so the inner loop reads are
// consecutive-lane (conflict-free); h0 reads are warp-broadcasts.
// ---------------------------------------------------------------------------
#define RPB 16   // rows per block
__global__ void __launch_bounds__(256) k_z(const float* __restrict__ h0,
                                           const float* __restrict__ w_fc,
                                           const float* __restrict__ w_attn) {
    __shared__ float wT[H_ * D_];          // wT[h*64 + d] = w_fc[d*64 + h]
    __shared__ float h0s[RPB * H_];
    __shared__ float red1[4][2][4], red2[4][2][4];

    const int t = threadIdx.x;
    const int row0 = blockIdx.x * RPB;

    // load w_fc transposed: consecutive idx -> consecutive d at fixed h
    for (int idx = t; idx < H_ * D_; idx += 256) {
        const int d = idx >> 6, h = idx & 63;
        wT[h * 64 + d] = w_fc[idx];
    }
    for (int idx = t; idx < RPB * H_; idx += 256)
        h0s[idx] = h0[row0 * H_ + idx];
    __syncthreads();

    const int d  = t & 63;
    const int rg = t >> 6;                 // 0..3 (4 rows each)
    const float* hb = &h0s[rg * 4 * H_];

    float acc0 = 0.f, acc1 = 0.f, acc2 = 0.f, acc3 = 0.f;
#pragma unroll
    for (int h = 0; h < H_; ++h) {
        const float w = wT[h * 64 + d];
        acc0 = fmaf(hb[0 * H_ + h], w, acc0);
        acc1 = fmaf(hb[1 * H_ + h], w, acc1);
        acc2 = fmaf(hb[2 * H_ + h], w, acc2);
        acc3 = fmaf(hb[3 * H_ + h], w, acc3);
    }

    const int r = row0 + rg * 4;
    g_z[(r + 0) * D_ + d] = acc0;
    g_z[(r + 1) * D_ + d] = acc1;
    g_z[(r + 2) * D_ + d] = acc2;
    g_z[(r + 3) * D_ + d] = acc3;

    // si/sj: dot each z row with a1/a2 across the 64 d's (2 warps per rg)
    const float a1 = __ldg(&w_attn[d]);
    const float a2 = __ldg(&w_attn[D_ + d]);
    float c1[4] = { acc0 * a1, acc1 * a1, acc2 * a1, acc3 * a1 };
    float c2[4] = { acc0 * a2, acc1 * a2, acc2 * a2, acc3 * a2 };
#pragma unroll
    for (int o = 16; o; o >>= 1) {
#pragma unroll
        for (int p = 0; p < 4; ++p) {
            c1[p] += __shfl_down_sync(0xffffffffu, c1[p], o);
            c2[p] += __shfl_down_sync(0xffffffffu, c2[p], o);
        }
    }
    const int half = (t >> 5) & 1;
    if ((t & 31) == 0) {
#pragma unroll
        for (int p = 0; p < 4; ++p) {
            red1[rg][half][p] = c1[p];
            red2[rg][half][p] = c2[p];
        }
    }
    __syncthreads();
    if (t < 16) {
        const int rg2 = t >> 2, p = t & 3;
        const int row = row0 + rg2 * 4 + p;
        g_sj[row] = red1[rg2][0][p] + red1[rg2][1][p];
        g_si[row] = red2[rg2][0][p] + red2[rg2][1][p];
    }
}

// ---------------------------------------------------------------------------
// k_row: one block per (b,i) row, 256 threads, streams 64KB of e with
// lane-contiguous float4 loads. 4-lane group completes the 16-feature dot
// via two shfl_xor; exp computed 4x redundantly (MUFU cost ~4us chip-wide),
// rowsum scaled by 0.25.
// rowsum[b,i] = sum_j exp(leaky_relu(si[b,i] + sj[b,j] + <e[b,i,j,:], a3>))
// ---------------------------------------------------------------------------
__global__ void __launch_bounds__(256) k_row(const float* __restrict__ e,
                                             const float* __restrict__ w_attn) {
    __shared__ float sjs[N_];
    __shared__ float red[8];

    const int row = blockIdx.x;      // b*N + i
    const int b = row >> 10;
    const int t = threadIdx.x;
    const int lane = t & 31;
    const int w = t >> 5;

#pragma unroll
    for (int j = t; j < N_; j += 256) sjs[j] = g_sj[b * N_ + j];
    __syncthreads();

    const int fg = (lane & 3) * 4;
    const float af0 = __ldg(&w_attn[2 * D_ + fg + 0]);
    const float af1 = __ldg(&w_attn[2 * D_ + fg + 1]);
    const float af2 = __ldg(&w_attn[2 * D_ + fg + 2]);
    const float af3 = __ldg(&w_attn[2 * D_ + fg + 3]);

    const float si = g_si[row];
    const float4* e4 = reinterpret_cast<const float4*>(e) + (size_t)row * (N_ * 4);

    float acc = 0.f;
#pragma unroll 8
    for (int idx4 = t; idx4 < N_ * 4; idx4 += 256) {
        const float4 v = __ldcs(&e4[idx4]);
        float p = v.x * af0;
        p = fmaf(v.y, af1, p);
        p = fmaf(v.z, af2, p);
        p = fmaf(v.w, af3, p);
        p += __shfl_xor_sync(0xffffffffu, p, 1);
        p += __shfl_xor_sync(0xffffffffu, p, 2);
        const int j = idx4 >> 2;
        float s = si + sjs[j] + p;
        s = (s >= 0.f) ? s : 0.01f * s;              // leaky_relu
        acc += __expf(s);
    }

#pragma unroll
    for (int o = 16; o; o >>= 1) acc += __shfl_down_sync(0xffffffffu, acc, o);
    if (lane == 0) red[w] = acc;
    __syncthreads();
    if (t == 0) {
        float s = 0.f;
#pragma unroll
        for (int k = 0; k < 8; ++k) s += red[k];
        g_rowsum[row] = 0.25f * s;
    }
}

// ---------------------------------------------------------------------------
// k_finish: one 64-thread block per row. Each block deterministically
// (redundantly) reduces its batch's 1024 rowsums (4KB, L2-resident), then
// out[row,d] = (rowsum[row]/total[b]) * z[row,d].
// ---------------------------------------------------------------------------
__global__ void __launch_bounds__(64) k_finish(float* __restrict__ out) {
    __shared__ float red[2];
    const int row = blockIdx.x;
    const int b = row >> 10;
    const int t = threadIdx.x;

    const float4* rs4 = reinterpret_cast<const float4*>(g_rowsum) + b * 256;
    float acc = 0.f;
#pragma unroll
    for (int k = t; k < 256; k += 64) {
        const float4 v = rs4[k];
        acc += (v.x + v.y) + (v.z + v.w);
    }
#pragma unroll
    for (int o = 16; o; o >>= 1) acc += __shfl_down_sync(0xffffffffu, acc, o);
    if ((t & 31) == 0) red[t >> 5] = acc;
    __syncthreads();
    const float total = red[0] + red[1];
    const float scale = g_rowsum[row] * (1.0f / total);
    out[row * D_ + t] = scale * g_z[row * D_ + t];
}

// ---------------------------------------------------------------------------
extern "C" void kernel_launch(void* const* d_in, const int* in_sizes, int n_in,
                              void* d_out, int out_size) {
    const float* h0     = (const float*)d_in[0];   // (B,N,H)
    const float* e      = (const float*)d_in[1];   // (B,N,N,FE)
    const float* w_fc   = (const float*)d_in[2];   // (D,H)
    const float* w_attn = (const float*)d_in[3];   // (2D+FE,)
    float* out = (float*)d_out;                    // (B,N,D)

    k_z<<<(B_ * N_) / RPB, 256>>>(h0, w_fc, w_attn);
    k_row<<<B_ * N_, 256>>>(e, w_attn);
    k_finish<<<B_ * N_, 64>>>(out);
}

// round 4
// speedup vs baseline: 2.1049x; 1.0407x over previous
#include <cuda_runtime.h>

// Problem constants
#define B_ 4
#define N_ 1024
#define H_ 64
#define D_ 64
#define FE_ 16

// Scratch (allocation-free: __device__ globals)
__device__ float g_z[B_ * N_ * D_];       // 1 MB
__device__ float g_si[B_ * N_];
__device__ float g_sj[B_ * N_];
__device__ float g_rowsum[B_ * N_];

// ---------------------------------------------------------------------------
// k_z v3: tiled GEMM. 512 blocks x 256 threads, 8 rows/block, 2 rows/thread.
// z[r,d] = sum_h h0[r,h] * w_fc[d,h];  sj[r]=z[r,:].a1, si[r]=z[r,:].a2
//  - wT staged transposed with +1 padding (65 floats/row): conflict-free on
//    BOTH the transpose store and the inner-loop load (R3 had a 32-way
//    conflict on the store).
//  - h0 broadcasts via float4 (1 LDS.128 per 4 h per row).
//  - 2-row register blocking halves wT smem traffic vs 1 row/thread.
// ---------------------------------------------------------------------------
#define RPB 8    // rows per block
#define WPITCH 65
__global__ void __launch_bounds__(256) k_z(const float* __restrict__ h0,
                                           const float* __restrict__ w_fc,
                                           const float* __restrict__ w_attn) {
    __shared__ float wT[H_ * WPITCH];      // wT[h*65 + d] = w_fc[d*64 + h]
    __shared__ __align__(16) float h0s[RPB * H_];
    __shared__ float red1[4][2][2], red2[4][2][2];

    const int t = threadIdx.x;
    const int row0 = blockIdx.x * RPB;

    // stage w_fc transposed; consecutive idx -> consecutive h at fixed d,
    // store addresses stride 65*4B -> conflict-free
    for (int idx = t; idx < H_ * D_; idx += 256) {
        const int d = idx >> 6, h = idx & 63;
        wT[h * WPITCH + d] = w_fc[idx];
    }
    for (int idx = t; idx < RPB * H_; idx += 256)
        h0s[idx] = h0[row0 * H_ + idx];
    __syncthreads();

    const int d  = t & 63;
    const int rg = t >> 6;                 // 0..3, each handles 2 rows
    const float4* h0v = reinterpret_cast<const float4*>(h0s);
    const int r0off = (rg * 2 + 0) * (H_ / 4);
    const int r1off = (rg * 2 + 1) * (H_ / 4);

    float acc0 = 0.f, acc1 = 0.f;
#pragma unroll
    for (int h4 = 0; h4 < H_ / 4; ++h4) {
        const float4 a0 = h0v[r0off + h4];
        const float4 a1 = h0v[r1off + h4];
        const float w0 = wT[(h4 * 4 + 0) * WPITCH + d];
        const float w1 = wT[(h4 * 4 + 1) * WPITCH + d];
        const float w2 = wT[(h4 * 4 + 2) * WPITCH + d];
        const float w3 = wT[(h4 * 4 + 3) * WPITCH + d];
        acc0 = fmaf(a0.x, w0, acc0); acc1 = fmaf(a1.x, w0, acc1);
        acc0 = fmaf(a0.y, w1, acc0); acc1 = fmaf(a1.y, w1, acc1);
        acc0 = fmaf(a0.z, w2, acc0); acc1 = fmaf(a1.z, w2, acc1);
        acc0 = fmaf(a0.w, w3, acc0); acc1 = fmaf(a1.w, w3, acc1);
    }

    const int r = row0 + rg * 2;
    g_z[(r + 0) * D_ + d] = acc0;
    g_z[(r + 1) * D_ + d] = acc1;

    // si/sj: dot z rows with a1/a2 across the 64 d's (2 warps per rg)
    const float a1w = __ldg(&w_attn[d]);
    const float a2w = __ldg(&w_attn[D_ + d]);
    float c1[2] = { acc0 * a1w, acc1 * a1w };
    float c2[2] = { acc0 * a2w, acc1 * a2w };
#pragma unroll
    for (int o = 16; o; o >>= 1) {
#pragma unroll
        for (int p = 0; p < 2; ++p) {
            c1[p] += __shfl_down_sync(0xffffffffu, c1[p], o);
            c2[p] += __shfl_down_sync(0xffffffffu, c2[p], o);
        }
    }
    const int half = (t >> 5) & 1;
    if ((t & 31) == 0) {
#pragma unroll
        for (int p = 0; p < 2; ++p) {
            red1[rg][half][p] = c1[p];
            red2[rg][half][p] = c2[p];
        }
    }
    __syncthreads();
    if (t < 8) {
        const int rg2 = t >> 1, p = t & 1;
        const int row = row0 + rg2 * 2 + p;
        g_sj[row] = red1[rg2][0][p] + red1[rg2][1][p];
        g_si[row] = red2[rg2][0][p] + red2[rg2][1][p];
    }
}

// ---------------------------------------------------------------------------
// k_row: one block per (b,i) row, 256 threads, streams 64KB of e with
// lane-contiguous float4 loads. 4-lane group completes the 16-feature dot
// via two shfl_xor; exp computed 4x redundantly, rowsum scaled by 0.25.
// rowsum[b,i] = sum_j exp(leaky_relu(si[b,i] + sj[b,j] + <e[b,i,j,:], a3>))
// ---------------------------------------------------------------------------
__global__ void __launch_bounds__(256) k_row(const float* __restrict__ e,
                                             const float* __restrict__ w_attn) {
    __shared__ float sjs[N_];
    __shared__ float red[8];

    const int row = blockIdx.x;      // b*N + i
    const int b = row >> 10;
    const int t = threadIdx.x;
    const int lane = t & 31;
    const int w = t >> 5;

#pragma unroll
    for (int j = t; j < N_; j += 256) sjs[j] = g_sj[b * N_ + j];
    __syncthreads();

    const int fg = (lane & 3) * 4;
    const float af0 = __ldg(&w_attn[2 * D_ + fg + 0]);
    const float af1 = __ldg(&w_attn[2 * D_ + fg + 1]);
    const float af2 = __ldg(&w_attn[2 * D_ + fg + 2]);
    const float af3 = __ldg(&w_attn[2 * D_ + fg + 3]);

    const float si = g_si[row];
    const float4* e4 = reinterpret_cast<const float4*>(e) + (size_t)row * (N_ * 4);

    float acc = 0.f;
#pragma unroll 8
    for (int idx4 = t; idx4 < N_ * 4; idx4 += 256) {
        const float4 v = __ldcs(&e4[idx4]);
        float p = v.x * af0;
        p = fmaf(v.y, af1, p);
        p = fmaf(v.z, af2, p);
        p = fmaf(v.w, af3, p);
        p += __shfl_xor_sync(0xffffffffu, p, 1);
        p += __shfl_xor_sync(0xffffffffu, p, 2);
        const int j = idx4 >> 2;
        float s = si + sjs[j] + p;
        s = (s >= 0.f) ? s : 0.01f * s;              // leaky_relu
        acc += __expf(s);
    }

#pragma unroll
    for (int o = 16; o; o >>= 1) acc += __shfl_down_sync(0xffffffffu, acc, o);
    if (lane == 0) red[w] = acc;
    __syncthreads();
    if (t == 0) {
        float s = 0.f;
#pragma unroll
        for (int k = 0; k < 8; ++k) s += red[k];
        g_rowsum[row] = 0.25f * s;
    }
}

// ---------------------------------------------------------------------------
// k_finish: one 64-thread block per row. Each block deterministically
// (redundantly) reduces its batch's 1024 rowsums (4KB, L2-resident), then
// out[row,d] = (rowsum[row]/total[b]) * z[row,d].
// ---------------------------------------------------------------------------
__global__ void __launch_bounds__(64) k_finish(float* __restrict__ out) {
    __shared__ float red[2];
    const int row = blockIdx.x;
    const int b = row >> 10;
    const int t = threadIdx.x;

    const float4* rs4 = reinterpret_cast<const float4*>(g_rowsum) + b * 256;
    float acc = 0.f;
#pragma unroll
    for (int k = t; k < 256; k += 64) {
        const float4 v = rs4[k];
        acc += (v.x + v.y) + (v.z + v.w);
    }
#pragma unroll
    for (int o = 16; o; o >>= 1) acc += __shfl_down_sync(0xffffffffu, acc, o);
    if ((t & 31) == 0) red[t >> 5] = acc;
    __syncthreads();
    const float total = red[0] + red[1];
    const float scale = g_rowsum[row] * (1.0f / total);
    out[row * D_ + t] = scale * g_z[row * D_ + t];
}

// ---------------------------------------------------------------------------
extern "C" void kernel_launch(void* const* d_in, const int* in_sizes, int n_in,
                              void* d_out, int out_size) {
    const float* h0     = (const float*)d_in[0];   // (B,N,H)
    const float* e      = (const float*)d_in[1];   // (B,N,N,FE)
    const float* w_fc   = (const float*)d_in[2];   // (D,H)
    const float* w_attn = (const float*)d_in[3];   // (2D+FE,)
    float* out = (float*)d_out;                    // (B,N,D)

    k_z<<<(B_ * N_) / RPB, 256>>>(h0, w_fc, w_attn);
    k_row<<<B_ * N_, 256>>>(e, w_attn);
    k_finish<<<B_ * N_, 64>>>(out);
}

// round 5
// speedup vs baseline: 2.2577x; 1.0726x over previous
#include <cuda_runtime.h>

// Problem constants
#define B_ 4
#define N_ 1024
#define H_ 64
#define D_ 64
#define FE_ 16

// Scratch (allocation-free: __device__ globals)
__device__ float g_z[B_ * N_ * D_];       // 1 MB
__device__ float g_si[B_ * N_];
__device__ float g_sj[B_ * N_];
__device__ float g_rowsum[B_ * N_];

// ---------------------------------------------------------------------------
// k_z v4: SINGLE-WAVE tiled GEMM. 128 blocks x 512 threads, 32 rows/block,
// 4 rows/thread. One block per SM -> total time ~= one block's critical path.
// z[r,d] = sum_h h0[r,h]*w_fc[d,h];  sj[r]=z[r,:].a1, si[r]=z[r,:].a2
// wT staged transposed with pitch 65 (conflict-free store+load);
// h0 read as float4 broadcasts.
// ---------------------------------------------------------------------------
#define RPB 32     // rows per block
#define WPITCH 65
__global__ void __launch_bounds__(512) k_z(const float* __restrict__ h0,
                                           const float* __restrict__ w_fc,
                                           const float* __restrict__ w_attn) {
    __shared__ float wT[H_ * WPITCH];               // wT[h*65+d] = w_fc[d*64+h]
    __shared__ __align__(16) float h0s[RPB * H_];   // 8 KB
    __shared__ float red1[8][2][4], red2[8][2][4];

    const int t = threadIdx.x;
    const int row0 = blockIdx.x * RPB;

    // stage w_fc transposed (store stride 65*4B: conflict-free)
#pragma unroll
    for (int idx = t; idx < H_ * D_; idx += 512) {
        const int d = idx >> 6, h = idx & 63;
        wT[h * WPITCH + d] = w_fc[idx];
    }
#pragma unroll
    for (int idx = t; idx < RPB * H_; idx += 512)
        h0s[idx] = h0[row0 * H_ + idx];
    __syncthreads();

    const int d  = t & 63;
    const int rg = t >> 6;                 // 0..7, each handles 4 rows
    const float4* h0v = reinterpret_cast<const float4*>(h0s);
    const int rbase = rg * 4;

    float acc0 = 0.f, acc1 = 0.f, acc2 = 0.f, acc3 = 0.f;
#pragma unroll
    for (int h4 = 0; h4 < H_ / 4; ++h4) {
        const float4 a0 = h0v[(rbase + 0) * (H_ / 4) + h4];
        const float4 a1 = h0v[(rbase + 1) * (H_ / 4) + h4];
        const float4 a2 = h0v[(rbase + 2) * (H_ / 4) + h4];
        const float4 a3 = h0v[(rbase + 3) * (H_ / 4) + h4];
        const float w0 = wT[(h4 * 4 + 0) * WPITCH + d];
        const float w1 = wT[(h4 * 4 + 1) * WPITCH + d];
        const float w2 = wT[(h4 * 4 + 2) * WPITCH + d];
        const float w3 = wT[(h4 * 4 + 3) * WPITCH + d];
        acc0 = fmaf(a0.x, w0, acc0); acc1 = fmaf(a1.x, w0, acc1);
        acc2 = fmaf(a2.x, w0, acc2); acc3 = fmaf(a3.x, w0, acc3);
        acc0 = fmaf(a0.y, w1, acc0); acc1 = fmaf(a1.y, w1, acc1);
        acc2 = fmaf(a2.y, w1, acc2); acc3 = fmaf(a3.y, w1, acc3);
        acc0 = fmaf(a0.z, w2, acc0); acc1 = fmaf(a1.z, w2, acc1);
        acc2 = fmaf(a2.z, w2, acc2); acc3 = fmaf(a3.z, w2, acc3);
        acc0 = fmaf(a0.w, w3, acc0); acc1 = fmaf(a1.w, w3, acc1);
        acc2 = fmaf(a2.w, w3, acc2); acc3 = fmaf(a3.w, w3, acc3);
    }

    const int r = row0 + rbase;
    g_z[(r + 0) * D_ + d] = acc0;
    g_z[(r + 1) * D_ + d] = acc1;
    g_z[(r + 2) * D_ + d] = acc2;
    g_z[(r + 3) * D_ + d] = acc3;

    // si/sj: dot z rows with a1/a2 across 64 d's (2 warps per row-group)
    const float a1w = __ldg(&w_attn[d]);
    const float a2w = __ldg(&w_attn[D_ + d]);
    float c1[4] = { acc0 * a1w, acc1 * a1w, acc2 * a1w, acc3 * a1w };
    float c2[4] = { acc0 * a2w, acc1 * a2w, acc2 * a2w, acc3 * a2w };
#pragma unroll
    for (int o = 16; o; o >>= 1) {
#pragma unroll
        for (int p = 0; p < 4; ++p) {
            c1[p] += __shfl_down_sync(0xffffffffu, c1[p], o);
            c2[p] += __shfl_down_sync(0xffffffffu, c2[p], o);
        }
    }
    const int half = (t >> 5) & 1;
    if ((t & 31) == 0) {
#pragma unroll
        for (int p = 0; p < 4; ++p) {
            red1[rg][half][p] = c1[p];
            red2[rg][half][p] = c2[p];
        }
    }
    __syncthreads();
    if (t < 32) {
        const int rg2 = t >> 2, p = t & 3;
        const int row = row0 + rg2 * 4 + p;
        g_sj[row] = red1[rg2][0][p] + red1[rg2][1][p];
        g_si[row] = red2[rg2][0][p] + red2[rg2][1][p];
    }
}

// ---------------------------------------------------------------------------
// k_row: one block per (b,i) row, 256 threads, streams 64KB of e with
// lane-contiguous float4 loads. 4-lane group completes the 16-feature dot
// via two shfl_xor; exp computed 4x redundantly, rowsum scaled by 0.25.
// rowsum[b,i] = sum_j exp(leaky_relu(si[b,i] + sj[b,j] + <e[b,i,j,:], a3>))
// (at the 256MB DRAM floor: ~37-38us)
// ---------------------------------------------------------------------------
__global__ void __launch_bounds__(256) k_row(const float* __restrict__ e,
                                             const float* __restrict__ w_attn) {
    __shared__ float sjs[N_];
    __shared__ float red[8];

    const int row = blockIdx.x;      // b*N + i
    const int b = row >> 10;
    const int t = threadIdx.x;
    const int lane = t & 31;
    const int w = t >> 5;

#pragma unroll
    for (int j = t; j < N_; j += 256) sjs[j] = g_sj[b * N_ + j];
    __syncthreads();

    const int fg = (lane & 3) * 4;
    const float af0 = __ldg(&w_attn[2 * D_ + fg + 0]);
    const float af1 = __ldg(&w_attn[2 * D_ + fg + 1]);
    const float af2 = __ldg(&w_attn[2 * D_ + fg + 2]);
    const float af3 = __ldg(&w_attn[2 * D_ + fg + 3]);

    const float si = g_si[row];
    const float4* e4 = reinterpret_cast<const float4*>(e) + (size_t)row * (N_ * 4);

    float acc = 0.f;
#pragma unroll 8
    for (int idx4 = t; idx4 < N_ * 4; idx4 += 256) {
        const float4 v = __ldcs(&e4[idx4]);
        float p = v.x * af0;
        p = fmaf(v.y, af1, p);
        p = fmaf(v.z, af2, p);
        p = fmaf(v.w, af3, p);
        p += __shfl_xor_sync(0xffffffffu, p, 1);
        p += __shfl_xor_sync(0xffffffffu, p, 2);
        const int j = idx4 >> 2;
        float s = si + sjs[j] + p;
        s = (s >= 0.f) ? s : 0.01f * s;              // leaky_relu
        acc += __expf(s);
    }

#pragma unroll
    for (int o = 16; o; o >>= 1) acc += __shfl_down_sync(0xffffffffu, acc, o);
    if (lane == 0) red[w] = acc;
    __syncthreads();
    if (t == 0) {
        float s = 0.f;
#pragma unroll
        for (int k = 0; k < 8; ++k) s += red[k];
        g_rowsum[row] = 0.25f * s;
    }
}

// ---------------------------------------------------------------------------
// k_finish: one 64-thread block per row. Each block deterministically
// (redundantly) reduces its batch's 1024 rowsums (4KB, L2-resident), then
// out[row,d] = (rowsum[row]/total[b]) * z[row,d].
// ---------------------------------------------------------------------------
__global__ void __launch_bounds__(64) k_finish(float* __restrict__ out) {
    __shared__ float red[2];
    const int row = blockIdx.x;
    const int b = row >> 10;
    const int t = threadIdx.x;

    const float4* rs4 = reinterpret_cast<const float4*>(g_rowsum) + b * 256;
    float acc = 0.f;
#pragma unroll
    for (int k = t; k < 256; k += 64) {
        const float4 v = rs4[k];
        acc += (v.x + v.y) + (v.z + v.w);
    }
#pragma unroll
    for (int o = 16; o; o >>= 1) acc += __shfl_down_sync(0xffffffffu, acc, o);
    if ((t & 31) == 0) red[t >> 5] = acc;
    __syncthreads();
    const float total = red[0] + red[1];
    const float scale = g_rowsum[row] * (1.0f / total);
    out[row * D_ + t] = scale * g_z[row * D_ + t];
}

// ---------------------------------------------------------------------------
extern "C" void kernel_launch(void* const* d_in, const int* in_sizes, int n_in,
                              void* d_out, int out_size) {
    const float* h0     = (const float*)d_in[0];   // (B,N,H)
    const float* e      = (const float*)d_in[1];   // (B,N,N,FE)
    const float* w_fc   = (const float*)d_in[2];   // (D,H)
    const float* w_attn = (const float*)d_in[3];   // (2D+FE,)
    float* out = (float*)d_out;                    // (B,N,D)

    k_z<<<(B_ * N_) / RPB, 512>>>(h0, w_fc, w_attn);
    k_row<<<B_ * N_, 256>>>(e, w_attn);
    k_finish<<<B_ * N_, 64>>>(out);
}